// round 12
// baseline (speedup 1.0000x reference)
#include <cuda_runtime.h>
#include <stdint.h>

#define N_SEG 128
#define S_VID 2048
#define HDIM  256
#define DDIM  512
#define RTOT  (N_SEG + S_VID)   // 2176
#define NEGV  (-1000.0f)
#define FULLMASK 0xffffffffu

__device__ float g_P[RTOT * HDIM];          // rows 0..127: A(+b1), rows 128..: B
__device__ float g_logitsT[S_VID * N_SEG];  // [s][n]
__device__ float g_logsigT[S_VID * N_SEG];  // [s][n]

typedef unsigned long long u64;

__device__ __forceinline__ u64 dup2(float a) {
    u64 d; asm("mov.b64 %0,{%1,%1};" : "=l"(d) : "f"(a)); return d;
}
__device__ __forceinline__ void unpack2(u64 v, float& lo, float& hi) {
    asm("mov.b64 {%0,%1},%2;" : "=f"(lo), "=f"(hi) : "l"(v));
}
__device__ __forceinline__ void fma2(u64& acc, u64 a, u64 b) {
    asm("fma.rn.f32x2 %0,%1,%2,%0;" : "+l"(acc) : "l"(a), "l"(b));
}

__device__ __forceinline__ uint32_t smem_u32(const void* p) {
    uint32_t a;
    asm("{ .reg .u64 t; cvta.to.shared.u64 t, %1; cvt.u32.u64 %0, t; }" : "=r"(a) : "l"(p));
    return a;
}
__device__ __forceinline__ void cpa16(uint32_t s, const void* g) {
    asm volatile("cp.async.cg.shared.global [%0], [%1], 16;" :: "r"(s), "l"(g));
}
__device__ __forceinline__ void cpa_commit() {
    asm volatile("cp.async.commit_group;");
}
template<int N> __device__ __forceinline__ void cpa_wait() {
    asm volatile("cp.async.wait_group %0;" :: "n"(N));
}

// shifts ncu's capture window so launch #6 = dp_k3 (memset = 2 launches)
__global__ void dummy_k() {}

// ============================================================
// K1: 128 rows x 128 h tile, BK=32, 512 threads, 4x8 microtile, f32x2
// ============================================================
__global__ __launch_bounds__(512) void gemm_k1(
    const float* __restrict__ seg, const float* __restrict__ vid,
    const float* __restrict__ W1, const float* __restrict__ b1)
{
    __shared__ float Xs[32][132];
    __shared__ float Ws[32][132];
    const int r0 = blockIdx.x * 128;
    const int h0 = blockIdx.y * 128;
    const int t  = threadIdx.x;
    const int tm = (t >> 4) * 4;   // 0..124 rows
    const int tn = (t & 15) * 8;   // 0..120 h
    const int koff = (r0 < N_SEG) ? 0 : DDIM;
    const float* xbase = (r0 < N_SEG) ? (seg + (size_t)r0 * DDIM)
                                      : (vid + (size_t)(r0 - N_SEG) * DDIM);

    u64 acc[4][4];
    #pragma unroll
    for (int i = 0; i < 4; i++)
        #pragma unroll
        for (int j = 0; j < 4; j++) acc[i][j] = 0ull;

    float4 xreg[2], wreg[2];
    #pragma unroll
    for (int p = 0; p < 2; p++) {
        int idx = t + p * 512;
        int rr = idx >> 3, fq = idx & 7;
        xreg[p] = *(const float4*)(xbase + (size_t)rr * DDIM + 4 * fq);
        wreg[p] = *(const float4*)(W1 + (size_t)(h0 + rr) * (2 * DDIM) + koff + 4 * fq);
    }

    for (int k0 = 0; k0 < DDIM; k0 += 32) {
        __syncthreads();
        #pragma unroll
        for (int p = 0; p < 2; p++) {
            int idx = t + p * 512;
            int rr = idx >> 3, fq = idx & 7;
            int col = rr ^ (4 * fq);
            Xs[4 * fq + 0][col] = xreg[p].x;
            Xs[4 * fq + 1][col] = xreg[p].y;
            Xs[4 * fq + 2][col] = xreg[p].z;
            Xs[4 * fq + 3][col] = xreg[p].w;
            Ws[4 * fq + 0][col] = wreg[p].x;
            Ws[4 * fq + 1][col] = wreg[p].y;
            Ws[4 * fq + 2][col] = wreg[p].z;
            Ws[4 * fq + 3][col] = wreg[p].w;
        }
        __syncthreads();
        if (k0 + 32 < DDIM) {
            #pragma unroll
            for (int p = 0; p < 2; p++) {
                int idx = t + p * 512;
                int rr = idx >> 3, fq = idx & 7;
                xreg[p] = *(const float4*)(xbase + (size_t)rr * DDIM + k0 + 32 + 4 * fq);
                wreg[p] = *(const float4*)(W1 + (size_t)(h0 + rr) * (2 * DDIM) + koff + k0 + 32 + 4 * fq);
            }
        }
        #pragma unroll
        for (int kk = 0; kk < 32; kk++) {
            int q4 = 4 * (kk >> 2);
            float4 av = *(const float4*)&Xs[kk][tm ^ q4];
            ulonglong2 w0 = *(const ulonglong2*)&Ws[kk][tn ^ q4];
            ulonglong2 w1 = *(const ulonglong2*)&Ws[kk][(tn + 4) ^ q4];
            u64 ad;
            ad = dup2(av.x);
            fma2(acc[0][0], ad, w0.x); fma2(acc[0][1], ad, w0.y);
            fma2(acc[0][2], ad, w1.x); fma2(acc[0][3], ad, w1.y);
            ad = dup2(av.y);
            fma2(acc[1][0], ad, w0.x); fma2(acc[1][1], ad, w0.y);
            fma2(acc[1][2], ad, w1.x); fma2(acc[1][3], ad, w1.y);
            ad = dup2(av.z);
            fma2(acc[2][0], ad, w0.x); fma2(acc[2][1], ad, w0.y);
            fma2(acc[2][2], ad, w1.x); fma2(acc[2][3], ad, w1.y);
            ad = dup2(av.w);
            fma2(acc[3][0], ad, w0.x); fma2(acc[3][1], ad, w0.y);
            fma2(acc[3][2], ad, w1.x); fma2(acc[3][3], ad, w1.y);
        }
    }

    #pragma unroll
    for (int i = 0; i < 4; i++) {
        int r = r0 + tm + i;
        #pragma unroll
        for (int jp = 0; jp < 4; jp++) {
            float v0, v1;
            unpack2(acc[i][jp], v0, v1);
            int h = h0 + tn + 2 * jp;
            if (r0 < N_SEG) { v0 += b1[h]; v1 += b1[h + 1]; }
            *(float2*)&g_P[(size_t)r * HDIM + h] = make_float2(v0, v1);
        }
    }
}

// ============================================================
// K2: 64 n x 32 s, BK=32, 512 threads, 2x2 scalar microtile  (frozen)
// ============================================================
__global__ __launch_bounds__(512) void fused_k2(
    const float* __restrict__ W2, const float* __restrict__ b2)
{
    __shared__ float As[32][68];
    __shared__ float Bs[32][36];
    __shared__ float w2s[32];
    const int n0 = blockIdx.x * 64;
    const int s0 = blockIdx.y * 32;
    const int t  = threadIdx.x;
    const int tn = (t & 31) * 2;
    const int ts = (t >> 5) * 2;
    const int rr = t >> 3, fq = t & 7;
    const float bb2 = b2[0];

    float acc00 = 0.f, acc01 = 0.f, acc10 = 0.f, acc11 = 0.f;

    float4 areg, breg; float wreg = 0.f;
    areg = *(const float4*)(g_P + (size_t)(n0 + rr) * HDIM + 4 * fq);
    if (t < 256) breg = *(const float4*)(g_P + (size_t)(N_SEG + s0 + rr) * HDIM + 4 * fq);
    if (t < 32)  wreg = W2[t];

    for (int k0 = 0; k0 < HDIM; k0 += 32) {
        __syncthreads();
        {
            int col = rr ^ (4 * fq);
            As[4 * fq + 0][col] = areg.x;
            As[4 * fq + 1][col] = areg.y;
            As[4 * fq + 2][col] = areg.z;
            As[4 * fq + 3][col] = areg.w;
            if (t < 256) {
                Bs[4 * fq + 0][col] = breg.x;
                Bs[4 * fq + 1][col] = breg.y;
                Bs[4 * fq + 2][col] = breg.z;
                Bs[4 * fq + 3][col] = breg.w;
            }
            if (t < 32) w2s[t] = wreg;
        }
        __syncthreads();
        if (k0 + 32 < HDIM) {
            areg = *(const float4*)(g_P + (size_t)(n0 + rr) * HDIM + k0 + 32 + 4 * fq);
            if (t < 256) breg = *(const float4*)(g_P + (size_t)(N_SEG + s0 + rr) * HDIM + k0 + 32 + 4 * fq);
            if (t < 32)  wreg = W2[k0 + 32 + t];
        }
        #pragma unroll
        for (int kk = 0; kk < 32; kk++) {
            int q4 = 4 * (kk >> 2);
            float2 an = *(const float2*)&As[kk][tn ^ q4];
            float2 bv = *(const float2*)&Bs[kk][ts ^ q4];
            float w = w2s[kk];
            acc00 += fmaxf(an.x + bv.x, 0.0f) * w;
            acc01 += fmaxf(an.x + bv.y, 0.0f) * w;
            acc10 += fmaxf(an.y + bv.x, 0.0f) * w;
            acc11 += fmaxf(an.y + bv.y, 0.0f) * w;
        }
    }

    float L[2][2] = {{acc00 + bb2, acc01 + bb2}, {acc10 + bb2, acc11 + bb2}};
    #pragma unroll
    for (int j = 0; j < 2; j++) {
        int s = s0 + ts + j;
        float L0 = L[0][j], L1 = L[1][j];
        *(float2*)&g_logitsT[(size_t)s * N_SEG + n0 + tn] = make_float2(L0, L1);
        float ls0 = fminf(L0, 0.0f) - __logf(1.0f + __expf(-fabsf(L0)));
        float ls1 = fminf(L1, 0.0f) - __logf(1.0f + __expf(-fabsf(L1)));
        *(float2*)&g_logsigT[(size_t)s * N_SEG + n0 + tn] = make_float2(ls0, ls1);
    }
}

// ============================================================
// K3 roles (256 threads):
//   warps 0-4 (t<160)  : cp.async loaders (R11 protocol, proven)
//   warp 5 (160..191)  : replay steps 15..0 of chunk c+1 (seed = bmids)
//   warp 6 (192..223)  : replay steps 31..16 of chunk c+1 (seed = bcols)
//   warp 7 (224..255)  : serial DP, NO bit ops; snapshots entry + mid state
// ============================================================
template<bool CLAMP>
__device__ __forceinline__ void dp_chunk(const float* __restrict__ buf, int c, int L,
                                         float& p0, float& p1, float& p2, float& p3,
                                         float* __restrict__ bmids)
{
    const int n0 = 4 * L;
    float4 lsA = *(const float4*)(buf + 31 * 128 + n0);
    float4 lsB = *(const float4*)(buf + 30 * 128 + n0);
    #pragma unroll
    for (int i = 31; i >= 0; i--) {
        float4 ls = lsA;
        lsA = lsB;
        if (i >= 2) lsB = *(const float4*)(buf + (i - 2) * 128 + n0);
        float nxt3 = __shfl_down_sync(FULLMASK, p0, 1);
        if (L == 31) nxt3 = 0.0f;               // n=127 adds 0
        float c0 = ls.x + p1;
        float c1 = ls.y + p2;
        float c2 = ls.z + p3;
        float c3 = ls.w + nxt3;
        float v0 = fmaxf(c0, p0);
        float v1 = fmaxf(c1, p1);
        float v2 = fmaxf(c2, p2);
        float v3 = fmaxf(c3, p3);
        if (CLAMP) {
            int s = c * 32 + i;
            v0 = (s >= n0     && s <= 1920 + n0) ? v0 : NEGV;
            v1 = (s >= n0 + 1 && s <= 1921 + n0) ? v1 : NEGV;
            v2 = (s >= n0 + 2 && s <= 1922 + n0) ? v2 : NEGV;
            v3 = (s >= n0 + 3 && s <= 1923 + n0) ? v3 : NEGV;
        }
        p0 = v0; p1 = v1; p2 = v2; p3 = v3;
        if (i == 16)   // state after step 16 = seed for lower-half replay
            *(float4*)(bmids + c * 128 + n0) = make_float4(p0, p1, p2, p3);
    }
}

// replay steps IHI..ILO of chunk cc; identical arithmetic; emits take bits.
template<bool CLAMP, int IHI, int ILO>
__device__ __forceinline__ void replay_half(const float* __restrict__ buf, int cc, int L,
                                            const float* __restrict__ seeds,
                                            unsigned* __restrict__ bitsOut, int shift)
{
    const int n0 = 4 * L;
    float4 sv = *(const float4*)(seeds + cc * 128 + n0);
    float p0 = sv.x, p1 = sv.y, p2 = sv.z, p3 = sv.w;
    unsigned a0 = 0, a1 = 0, a2 = 0, a3 = 0;
    #pragma unroll
    for (int i = IHI; i >= ILO; i--) {
        float4 ls = *(const float4*)(buf + i * 128 + n0);
        float nxt3 = __shfl_down_sync(FULLMASK, p0, 1);
        if (L == 31) nxt3 = 0.0f;
        float c0 = ls.x + p1;
        float c1 = ls.y + p2;
        float c2 = ls.z + p3;
        float c3 = ls.w + nxt3;
        a0 = a0 + a0 + (unsigned)(c0 >= p0);
        a1 = a1 + a1 + (unsigned)(c1 >= p1);
        a2 = a2 + a2 + (unsigned)(c2 >= p2);
        a3 = a3 + a3 + (unsigned)(c3 >= p3);
        float v0 = fmaxf(c0, p0);
        float v1 = fmaxf(c1, p1);
        float v2 = fmaxf(c2, p2);
        float v3 = fmaxf(c3, p3);
        if (CLAMP) {
            int s = cc * 32 + i;
            v0 = (s >= n0     && s <= 1920 + n0) ? v0 : NEGV;
            v1 = (s >= n0 + 1 && s <= 1921 + n0) ? v1 : NEGV;
            v2 = (s >= n0 + 2 && s <= 1922 + n0) ? v2 : NEGV;
            v3 = (s >= n0 + 3 && s <= 1923 + n0) ? v3 : NEGV;
        }
        p0 = v0; p1 = v1; p2 = v2; p3 = v3;
    }
    *(uint4*)(bitsOut + cc * 128 + n0) =
        make_uint4(a0 << shift, a1 << shift, a2 << shift, a3 << shift);
}

// async loader: 160 lanes, 1024 float4s per chunk, fire-and-forget
__device__ __forceinline__ void load_chunk_async(const float* __restrict__ src,
                                                 uint32_t dst_s, int lt)
{
    #pragma unroll
    for (int j = 0; j < 7; j++) {
        int i = lt + 160 * j;
        if (i < 1024) cpa16(dst_s + i * 16, src + i * 4);
    }
    cpa_commit();
}

__global__ __launch_bounds__(256) void dp_k3(float* __restrict__ out, int out_size)
{
    extern __shared__ unsigned char smraw[];
    float*    lsbuf    = (float*)smraw;                      // [4][4096] 64KB ring
    float*    bcols    = lsbuf + 4 * 4096;                   // [64][128] 32KB
    float*    bmids    = bcols + 64 * 128;                   // [64][128] 32KB
    unsigned* bitsLo   = (unsigned*)(bmids + 64 * 128);      // [64][128] 32KB
    unsigned* bitsHi   = bitsLo + 64 * 128;                  // [64][128] 32KB
    int*      alignArr = (int*)(bitsHi + 64 * 128);          // [128]
    float*    redbuf   = (float*)(alignArr + 128);           // [4]

    const int t = threadIdx.x;
    const int L = t & 31;
    const uint32_t ls_s = smem_u32(lsbuf);

    if (t < 128) alignArr[t] = 0;
    if (t < 160) {
        load_chunk_async(g_logsigT + 63 * 4096, ls_s + (63 & 3) * 16384, t);
        load_chunk_async(g_logsigT + 62 * 4096, ls_s + (62 & 3) * 16384, t);
        cpa_wait<1>();   // chunk 63 complete before the first DP read
    }
    __syncthreads();

    float p0 = NEGV, p1 = NEGV, p2 = NEGV, p3 = NEGV;
    for (int c = 63; c >= 0; c--) {
        if (t >= 224) {
            // entry-state snapshot = seed for upper-half replay of chunk c
            *(float4*)(bcols + c * 128 + 4 * L) = make_float4(p0, p1, p2, p3);
            const float* buf = lsbuf + (c & 3) * 4096;
            if (c >= 4 && c <= 59) dp_chunk<false>(buf, c, L, p0, p1, p2, p3, bmids);
            else                   dp_chunk<true >(buf, c, L, p0, p1, p2, p3, bmids);
        } else if (t >= 192) {
            if (c < 63) {
                int cc = c + 1;
                const float* buf = lsbuf + (cc & 3) * 4096;
                if (cc >= 4 && cc <= 59) replay_half<false, 31, 16>(buf, cc, L, bcols, bitsHi, 16);
                else                     replay_half<true , 31, 16>(buf, cc, L, bcols, bitsHi, 16);
            }
        } else if (t >= 160) {
            if (c < 63) {
                int cc = c + 1;
                const float* buf = lsbuf + (cc & 3) * 4096;
                if (cc >= 4 && cc <= 59) replay_half<false, 15, 0>(buf, cc, L, bmids, bitsLo, 0);
                else                     replay_half<true , 15, 0>(buf, cc, L, bmids, bitsLo, 0);
            }
        } else {
            if (c >= 2) {
                load_chunk_async(g_logsigT + (size_t)(c - 2) * 4096,
                                 ls_s + ((c - 2) & 3) * 16384, t);
                cpa_wait<1>();   // newest pending = chunk c-2; chunk c-1 done
            } else if (c == 1) {
                cpa_wait<0>();   // chunk 0 done before final iteration
            }
        }
        __syncthreads();
    }
    // epilogue: replay chunk 0 (slot 0 untouched since it was loaded)
    if (t >= 192 && t < 224)
        replay_half<true, 31, 16>(lsbuf + 0, 0, L, bcols, bitsHi, 16);
    else if (t >= 160 && t < 192)
        replay_half<true, 15, 0>(lsbuf + 0, 0, L, bmids, bitsLo, 0);
    __syncthreads();

    // walk: first set take-bit at s >= scur per n (equivalent to ref scan)
    if (t == 0) {
        int scur = 0;
        for (int n = 0; n < 128; n++) {
            int wdi = scur >> 5;
            unsigned word = (bitsLo[wdi * 128 + n] | bitsHi[wdi * 128 + n])
                            & (0xFFFFFFFFu << (scur & 31));
            while (word == 0) {
                wdi++;
                if (wdi >= 64) break;
                word = bitsLo[wdi * 128 + n] | bitsHi[wdi * 128 + n];
            }
            if (wdi >= 64) break;
            int s = wdi * 32 + (__ffs(word) - 1);
            alignArr[n] = s;
            scur = s + 1;
            if (scur >= S_VID) break;
        }
    }
    __syncthreads();

    // outputs
    if (t < 128) {
        int a = alignArr[t];
        out[(size_t)(S_VID + t) * RTOT + a] = 1.0f;
        float v = g_logitsT[(size_t)a * N_SEG + t];
        #pragma unroll
        for (int o = 16; o; o >>= 1) v += __shfl_down_sync(FULLMASK, v, o);
        if ((t & 31) == 0) redbuf[t >> 5] = v;
    }
    __syncthreads();
    if (t == 0) {
        float sum = redbuf[0] + redbuf[1] + redbuf[2] + redbuf[3];
        if (out_size > RTOT * RTOT) out[(size_t)RTOT * RTOT] = sum * (1.0f / 128.0f);
    }
}

// ============================================================
extern "C" void kernel_launch(void* const* d_in, const int* in_sizes, int n_in,
                              void* d_out, int out_size)
{
    const float* seg = (const float*)d_in[0];
    const float* vid = (const float*)d_in[1];
    const float* W1  = (const float*)d_in[2];
    const float* b1  = (const float*)d_in[3];
    const float* W2  = (const float*)d_in[4];
    const float* b2  = (const float*)d_in[5];
    float* out = (float*)d_out;

    cudaMemsetAsync(out, 0, (size_t)out_size * sizeof(float), 0);  // ~2 launches
    dummy_k<<<1, 32>>>();
    gemm_k1<<<dim3(17, 2), 512>>>(seg, vid, W1, b1);
    fused_k2<<<dim3(2, 64), 512>>>(W2, b2);

    const int smem_k3 = (4 * 4096 + 2 * 64 * 128) * 4 + 2 * 64 * 128 * 4 + 128 * 4 + 4 * 4;
    cudaFuncSetAttribute(dp_k3, cudaFuncAttributeMaxDynamicSharedMemorySize, smem_k3);
    dp_k3<<<1, 256, smem_k3>>>(out, out_size);
}

// round 13
// speedup vs baseline: 1.5719x; 1.5719x over previous
#include <cuda_runtime.h>
#include <stdint.h>

#define N_SEG 128
#define S_VID 2048
#define HDIM  256
#define DDIM  512
#define RTOT  (N_SEG + S_VID)   // 2176
#define NEGV  (-1000.0f)
#define FULLMASK 0xffffffffu

__device__ float g_P[RTOT * HDIM];          // rows 0..127: A(+b1), rows 128..: B
__device__ float g_logitsT[S_VID * N_SEG];  // [s][n]
__device__ float g_logsigT[S_VID * N_SEG];  // [s][n]

typedef unsigned long long u64;

__device__ __forceinline__ u64 dup2(float a) {
    u64 d; asm("mov.b64 %0,{%1,%1};" : "=l"(d) : "f"(a)); return d;
}
__device__ __forceinline__ void unpack2(u64 v, float& lo, float& hi) {
    asm("mov.b64 {%0,%1},%2;" : "=f"(lo), "=f"(hi) : "l"(v));
}
__device__ __forceinline__ void fma2(u64& acc, u64 a, u64 b) {
    asm("fma.rn.f32x2 %0,%1,%2,%0;" : "+l"(acc) : "l"(a), "l"(b));
}

__device__ __forceinline__ uint32_t smem_u32(const void* p) {
    uint32_t a;
    asm("{ .reg .u64 t; cvta.to.shared.u64 t, %1; cvt.u32.u64 %0, t; }" : "=r"(a) : "l"(p));
    return a;
}
__device__ __forceinline__ void cpa16(uint32_t s, const void* g) {
    asm volatile("cp.async.cg.shared.global [%0], [%1], 16;" :: "r"(s), "l"(g));
}
__device__ __forceinline__ void cpa_commit() {
    asm volatile("cp.async.commit_group;");
}
template<int N> __device__ __forceinline__ void cpa_wait() {
    asm volatile("cp.async.wait_group %0;" :: "n"(N));
}

// shifts ncu's capture window so launch #6 = dp_k3 (memset = 2 launches)
__global__ void dummy_k() {}

// ============================================================
// K1: 64 rows x 64 h, BK=32, 512 threads, 2x4 microtile, f32x2
//     (reverted to proven R3/R11 config: 62 regs, 28.4 us)
// ============================================================
__global__ __launch_bounds__(512) void gemm_k1(
    const float* __restrict__ seg, const float* __restrict__ vid,
    const float* __restrict__ W1, const float* __restrict__ b1)
{
    __shared__ float Xs[32][68];
    __shared__ float Ws[32][68];
    const int r0 = blockIdx.x * 64;
    const int h0 = blockIdx.y * 64;
    const int t  = threadIdx.x;
    const int tm = (t >> 4) * 2;
    const int tn = (t & 15) * 4;
    const int koff = (r0 < N_SEG) ? 0 : DDIM;
    const float* xbase = (r0 < N_SEG) ? (seg + (size_t)r0 * DDIM)
                                      : (vid + (size_t)(r0 - N_SEG) * DDIM);
    const int rr = t >> 3, fq = t & 7;

    u64 acc[2][2];
    acc[0][0] = acc[0][1] = acc[1][0] = acc[1][1] = 0ull;

    float4 xreg, wreg;
    xreg = *(const float4*)(xbase + (size_t)rr * DDIM + 4 * fq);
    wreg = *(const float4*)(W1 + (size_t)(h0 + rr) * (2 * DDIM) + koff + 4 * fq);

    for (int k0 = 0; k0 < DDIM; k0 += 32) {
        __syncthreads();
        {
            int col = rr ^ (4 * fq);
            Xs[4 * fq + 0][col] = xreg.x;
            Xs[4 * fq + 1][col] = xreg.y;
            Xs[4 * fq + 2][col] = xreg.z;
            Xs[4 * fq + 3][col] = xreg.w;
            Ws[4 * fq + 0][col] = wreg.x;
            Ws[4 * fq + 1][col] = wreg.y;
            Ws[4 * fq + 2][col] = wreg.z;
            Ws[4 * fq + 3][col] = wreg.w;
        }
        __syncthreads();
        if (k0 + 32 < DDIM) {
            xreg = *(const float4*)(xbase + (size_t)rr * DDIM + k0 + 32 + 4 * fq);
            wreg = *(const float4*)(W1 + (size_t)(h0 + rr) * (2 * DDIM) + koff + k0 + 32 + 4 * fq);
        }
        #pragma unroll
        for (int kk = 0; kk < 32; kk++) {
            int q4 = 4 * (kk >> 2);
            float2 av = *(const float2*)&Xs[kk][tm ^ q4];
            ulonglong2 wv = *(const ulonglong2*)&Ws[kk][tn ^ q4];
            u64 a0 = dup2(av.x), a1 = dup2(av.y);
            fma2(acc[0][0], a0, wv.x); fma2(acc[0][1], a0, wv.y);
            fma2(acc[1][0], a1, wv.x); fma2(acc[1][1], a1, wv.y);
        }
    }

    #pragma unroll
    for (int i = 0; i < 2; i++) {
        int r = r0 + tm + i;
        #pragma unroll
        for (int jp = 0; jp < 2; jp++) {
            float v0, v1;
            unpack2(acc[i][jp], v0, v1);
            int h = h0 + tn + 2 * jp;
            if (r0 < N_SEG) { v0 += b1[h]; v1 += b1[h + 1]; }
            *(float2*)&g_P[(size_t)r * HDIM + h] = make_float2(v0, v1);
        }
    }
}

// ============================================================
// K2: 64 n x 32 s, BK=32, 512 threads, 2x2 scalar microtile  (frozen)
// ============================================================
__global__ __launch_bounds__(512) void fused_k2(
    const float* __restrict__ W2, const float* __restrict__ b2)
{
    __shared__ float As[32][68];
    __shared__ float Bs[32][36];
    __shared__ float w2s[32];
    const int n0 = blockIdx.x * 64;
    const int s0 = blockIdx.y * 32;
    const int t  = threadIdx.x;
    const int tn = (t & 31) * 2;
    const int ts = (t >> 5) * 2;
    const int rr = t >> 3, fq = t & 7;
    const float bb2 = b2[0];

    float acc00 = 0.f, acc01 = 0.f, acc10 = 0.f, acc11 = 0.f;

    float4 areg, breg; float wreg = 0.f;
    areg = *(const float4*)(g_P + (size_t)(n0 + rr) * HDIM + 4 * fq);
    if (t < 256) breg = *(const float4*)(g_P + (size_t)(N_SEG + s0 + rr) * HDIM + 4 * fq);
    if (t < 32)  wreg = W2[t];

    for (int k0 = 0; k0 < HDIM; k0 += 32) {
        __syncthreads();
        {
            int col = rr ^ (4 * fq);
            As[4 * fq + 0][col] = areg.x;
            As[4 * fq + 1][col] = areg.y;
            As[4 * fq + 2][col] = areg.z;
            As[4 * fq + 3][col] = areg.w;
            if (t < 256) {
                Bs[4 * fq + 0][col] = breg.x;
                Bs[4 * fq + 1][col] = breg.y;
                Bs[4 * fq + 2][col] = breg.z;
                Bs[4 * fq + 3][col] = breg.w;
            }
            if (t < 32) w2s[t] = wreg;
        }
        __syncthreads();
        if (k0 + 32 < HDIM) {
            areg = *(const float4*)(g_P + (size_t)(n0 + rr) * HDIM + k0 + 32 + 4 * fq);
            if (t < 256) breg = *(const float4*)(g_P + (size_t)(N_SEG + s0 + rr) * HDIM + k0 + 32 + 4 * fq);
            if (t < 32)  wreg = W2[k0 + 32 + t];
        }
        #pragma unroll
        for (int kk = 0; kk < 32; kk++) {
            int q4 = 4 * (kk >> 2);
            float2 an = *(const float2*)&As[kk][tn ^ q4];
            float2 bv = *(const float2*)&Bs[kk][ts ^ q4];
            float w = w2s[kk];
            acc00 += fmaxf(an.x + bv.x, 0.0f) * w;
            acc01 += fmaxf(an.x + bv.y, 0.0f) * w;
            acc10 += fmaxf(an.y + bv.x, 0.0f) * w;
            acc11 += fmaxf(an.y + bv.y, 0.0f) * w;
        }
    }

    float L[2][2] = {{acc00 + bb2, acc01 + bb2}, {acc10 + bb2, acc11 + bb2}};
    #pragma unroll
    for (int j = 0; j < 2; j++) {
        int s = s0 + ts + j;
        float L0 = L[0][j], L1 = L[1][j];
        *(float2*)&g_logitsT[(size_t)s * N_SEG + n0 + tn] = make_float2(L0, L1);
        float ls0 = fminf(L0, 0.0f) - __logf(1.0f + __expf(-fabsf(L0)));
        float ls1 = fminf(L1, 0.0f) - __logf(1.0f + __expf(-fabsf(L1)));
        *(float2*)&g_logsigT[(size_t)s * N_SEG + n0 + tn] = make_float2(ls0, ls1);
    }
}

// ============================================================
// K3 roles (256 threads)  — R12 version (52.5 us cold, proven):
//   warps 0-4 (t<160)  : cp.async loaders (R11 protocol)
//   warp 5 (160..191)  : replay steps 15..0 of chunk c+1 (seed = bmids)
//   warp 6 (192..223)  : replay steps 31..16 of chunk c+1 (seed = bcols)
//   warp 7 (224..255)  : serial DP, NO bit ops; snapshots entry + mid state
// ============================================================
template<bool CLAMP>
__device__ __forceinline__ void dp_chunk(const float* __restrict__ buf, int c, int L,
                                         float& p0, float& p1, float& p2, float& p3,
                                         float* __restrict__ bmids)
{
    const int n0 = 4 * L;
    float4 lsA = *(const float4*)(buf + 31 * 128 + n0);
    float4 lsB = *(const float4*)(buf + 30 * 128 + n0);
    #pragma unroll
    for (int i = 31; i >= 0; i--) {
        float4 ls = lsA;
        lsA = lsB;
        if (i >= 2) lsB = *(const float4*)(buf + (i - 2) * 128 + n0);
        float nxt3 = __shfl_down_sync(FULLMASK, p0, 1);
        if (L == 31) nxt3 = 0.0f;               // n=127 adds 0
        float c0 = ls.x + p1;
        float c1 = ls.y + p2;
        float c2 = ls.z + p3;
        float c3 = ls.w + nxt3;
        float v0 = fmaxf(c0, p0);
        float v1 = fmaxf(c1, p1);
        float v2 = fmaxf(c2, p2);
        float v3 = fmaxf(c3, p3);
        if (CLAMP) {
            int s = c * 32 + i;
            v0 = (s >= n0     && s <= 1920 + n0) ? v0 : NEGV;
            v1 = (s >= n0 + 1 && s <= 1921 + n0) ? v1 : NEGV;
            v2 = (s >= n0 + 2 && s <= 1922 + n0) ? v2 : NEGV;
            v3 = (s >= n0 + 3 && s <= 1923 + n0) ? v3 : NEGV;
        }
        p0 = v0; p1 = v1; p2 = v2; p3 = v3;
        if (i == 16)   // state after step 16 = seed for lower-half replay
            *(float4*)(bmids + c * 128 + n0) = make_float4(p0, p1, p2, p3);
    }
}

// replay steps IHI..ILO of chunk cc; identical arithmetic; emits take bits.
template<bool CLAMP, int IHI, int ILO>
__device__ __forceinline__ void replay_half(const float* __restrict__ buf, int cc, int L,
                                            const float* __restrict__ seeds,
                                            unsigned* __restrict__ bitsOut, int shift)
{
    const int n0 = 4 * L;
    float4 sv = *(const float4*)(seeds + cc * 128 + n0);
    float p0 = sv.x, p1 = sv.y, p2 = sv.z, p3 = sv.w;
    unsigned a0 = 0, a1 = 0, a2 = 0, a3 = 0;
    #pragma unroll
    for (int i = IHI; i >= ILO; i--) {
        float4 ls = *(const float4*)(buf + i * 128 + n0);
        float nxt3 = __shfl_down_sync(FULLMASK, p0, 1);
        if (L == 31) nxt3 = 0.0f;
        float c0 = ls.x + p1;
        float c1 = ls.y + p2;
        float c2 = ls.z + p3;
        float c3 = ls.w + nxt3;
        a0 = a0 + a0 + (unsigned)(c0 >= p0);
        a1 = a1 + a1 + (unsigned)(c1 >= p1);
        a2 = a2 + a2 + (unsigned)(c2 >= p2);
        a3 = a3 + a3 + (unsigned)(c3 >= p3);
        float v0 = fmaxf(c0, p0);
        float v1 = fmaxf(c1, p1);
        float v2 = fmaxf(c2, p2);
        float v3 = fmaxf(c3, p3);
        if (CLAMP) {
            int s = cc * 32 + i;
            v0 = (s >= n0     && s <= 1920 + n0) ? v0 : NEGV;
            v1 = (s >= n0 + 1 && s <= 1921 + n0) ? v1 : NEGV;
            v2 = (s >= n0 + 2 && s <= 1922 + n0) ? v2 : NEGV;
            v3 = (s >= n0 + 3 && s <= 1923 + n0) ? v3 : NEGV;
        }
        p0 = v0; p1 = v1; p2 = v2; p3 = v3;
    }
    *(uint4*)(bitsOut + cc * 128 + n0) =
        make_uint4(a0 << shift, a1 << shift, a2 << shift, a3 << shift);
}

// async loader: 160 lanes, 1024 float4s per chunk, fire-and-forget
__device__ __forceinline__ void load_chunk_async(const float* __restrict__ src,
                                                 uint32_t dst_s, int lt)
{
    #pragma unroll
    for (int j = 0; j < 7; j++) {
        int i = lt + 160 * j;
        if (i < 1024) cpa16(dst_s + i * 16, src + i * 4);
    }
    cpa_commit();
}

__global__ __launch_bounds__(256) void dp_k3(float* __restrict__ out, int out_size)
{
    extern __shared__ unsigned char smraw[];
    float*    lsbuf    = (float*)smraw;                      // [4][4096] 64KB ring
    float*    bcols    = lsbuf + 4 * 4096;                   // [64][128] 32KB
    float*    bmids    = bcols + 64 * 128;                   // [64][128] 32KB
    unsigned* bitsLo   = (unsigned*)(bmids + 64 * 128);      // [64][128] 32KB
    unsigned* bitsHi   = bitsLo + 64 * 128;                  // [64][128] 32KB
    int*      alignArr = (int*)(bitsHi + 64 * 128);          // [128]
    float*    redbuf   = (float*)(alignArr + 128);           // [4]

    const int t = threadIdx.x;
    const int L = t & 31;
    const uint32_t ls_s = smem_u32(lsbuf);

    if (t < 128) alignArr[t] = 0;
    if (t < 160) {
        load_chunk_async(g_logsigT + 63 * 4096, ls_s + (63 & 3) * 16384, t);
        load_chunk_async(g_logsigT + 62 * 4096, ls_s + (62 & 3) * 16384, t);
        cpa_wait<1>();   // chunk 63 complete before the first DP read
    }
    __syncthreads();

    float p0 = NEGV, p1 = NEGV, p2 = NEGV, p3 = NEGV;
    for (int c = 63; c >= 0; c--) {
        if (t >= 224) {
            // entry-state snapshot = seed for upper-half replay of chunk c
            *(float4*)(bcols + c * 128 + 4 * L) = make_float4(p0, p1, p2, p3);
            const float* buf = lsbuf + (c & 3) * 4096;
            if (c >= 4 && c <= 59) dp_chunk<false>(buf, c, L, p0, p1, p2, p3, bmids);
            else                   dp_chunk<true >(buf, c, L, p0, p1, p2, p3, bmids);
        } else if (t >= 192) {
            if (c < 63) {
                int cc = c + 1;
                const float* buf = lsbuf + (cc & 3) * 4096;
                if (cc >= 4 && cc <= 59) replay_half<false, 31, 16>(buf, cc, L, bcols, bitsHi, 16);
                else                     replay_half<true , 31, 16>(buf, cc, L, bcols, bitsHi, 16);
            }
        } else if (t >= 160) {
            if (c < 63) {
                int cc = c + 1;
                const float* buf = lsbuf + (cc & 3) * 4096;
                if (cc >= 4 && cc <= 59) replay_half<false, 15, 0>(buf, cc, L, bmids, bitsLo, 0);
                else                     replay_half<true , 15, 0>(buf, cc, L, bmids, bitsLo, 0);
            }
        } else {
            if (c >= 2) {
                load_chunk_async(g_logsigT + (size_t)(c - 2) * 4096,
                                 ls_s + ((c - 2) & 3) * 16384, t);
                cpa_wait<1>();   // newest pending = chunk c-2; chunk c-1 done
            } else if (c == 1) {
                cpa_wait<0>();   // chunk 0 done before final iteration
            }
        }
        __syncthreads();
    }
    // epilogue: replay chunk 0 (slot 0 untouched since it was loaded)
    if (t >= 192 && t < 224)
        replay_half<true, 31, 16>(lsbuf + 0, 0, L, bcols, bitsHi, 16);
    else if (t >= 160 && t < 192)
        replay_half<true, 15, 0>(lsbuf + 0, 0, L, bmids, bitsLo, 0);
    __syncthreads();

    // walk: first set take-bit at s >= scur per n (equivalent to ref scan)
    if (t == 0) {
        int scur = 0;
        for (int n = 0; n < 128; n++) {
            int wdi = scur >> 5;
            unsigned word = (bitsLo[wdi * 128 + n] | bitsHi[wdi * 128 + n])
                            & (0xFFFFFFFFu << (scur & 31));
            while (word == 0) {
                wdi++;
                if (wdi >= 64) break;
                word = bitsLo[wdi * 128 + n] | bitsHi[wdi * 128 + n];
            }
            if (wdi >= 64) break;
            int s = wdi * 32 + (__ffs(word) - 1);
            alignArr[n] = s;
            scur = s + 1;
            if (scur >= S_VID) break;
        }
    }
    __syncthreads();

    // outputs
    if (t < 128) {
        int a = alignArr[t];
        out[(size_t)(S_VID + t) * RTOT + a] = 1.0f;
        float v = g_logitsT[(size_t)a * N_SEG + t];
        #pragma unroll
        for (int o = 16; o; o >>= 1) v += __shfl_down_sync(FULLMASK, v, o);
        if ((t & 31) == 0) redbuf[t >> 5] = v;
    }
    __syncthreads();
    if (t == 0) {
        float sum = redbuf[0] + redbuf[1] + redbuf[2] + redbuf[3];
        if (out_size > RTOT * RTOT) out[(size_t)RTOT * RTOT] = sum * (1.0f / 128.0f);
    }
}

// ============================================================
extern "C" void kernel_launch(void* const* d_in, const int* in_sizes, int n_in,
                              void* d_out, int out_size)
{
    const float* seg = (const float*)d_in[0];
    const float* vid = (const float*)d_in[1];
    const float* W1  = (const float*)d_in[2];
    const float* b1  = (const float*)d_in[3];
    const float* W2  = (const float*)d_in[4];
    const float* b2  = (const float*)d_in[5];
    float* out = (float*)d_out;

    cudaMemsetAsync(out, 0, (size_t)out_size * sizeof(float), 0);  // ~2 launches
    dummy_k<<<1, 32>>>();
    gemm_k1<<<dim3(34, 4), 512>>>(seg, vid, W1, b1);
    fused_k2<<<dim3(2, 64), 512>>>(W2, b2);

    const int smem_k3 = (4 * 4096 + 2 * 64 * 128) * 4 + 2 * 64 * 128 * 4 + 128 * 4 + 4 * 4;
    cudaFuncSetAttribute(dp_k3, cudaFuncAttributeMaxDynamicSharedMemorySize, smem_k3);
    dp_k3<<<1, 256, smem_k3>>>(out, out_size);
}

// round 14
// speedup vs baseline: 1.7087x; 1.0870x over previous
#include <cuda_runtime.h>
#include <stdint.h>

#define N_SEG 128
#define S_VID 2048
#define HDIM  256
#define DDIM  512
#define KHALF 256
#define RTOT  (N_SEG + S_VID)   // 2176
#define NEGV  (-1000.0f)
#define FULLMASK 0xffffffffu

__device__ float g_P1[RTOT * HDIM];         // split-K partial, k in [0,256)
__device__ float g_P2[RTOT * HDIM];         // split-K partial, k in [256,512)
__device__ float g_P[RTOT * HDIM];          // reduced: rows 0..127 A(+b1), 128.. B
__device__ float g_logitsT[S_VID * N_SEG];  // [s][n]
__device__ float g_logsigT[S_VID * N_SEG];  // [s][n]

typedef unsigned long long u64;

__device__ __forceinline__ u64 dup2(float a) {
    u64 d; asm("mov.b64 %0,{%1,%1};" : "=l"(d) : "f"(a)); return d;
}
__device__ __forceinline__ void unpack2(u64 v, float& lo, float& hi) {
    asm("mov.b64 {%0,%1},%2;" : "=f"(lo), "=f"(hi) : "l"(v));
}
__device__ __forceinline__ void fma2(u64& acc, u64 a, u64 b) {
    asm("fma.rn.f32x2 %0,%1,%2,%0;" : "+l"(acc) : "l"(a), "l"(b));
}

__device__ __forceinline__ uint32_t smem_u32(const void* p) {
    uint32_t a;
    asm("{ .reg .u64 t; cvta.to.shared.u64 t, %1; cvt.u32.u64 %0, t; }" : "=r"(a) : "l"(p));
    return a;
}
__device__ __forceinline__ void cpa16(uint32_t s, const void* g) {
    asm volatile("cp.async.cg.shared.global [%0], [%1], 16;" :: "r"(s), "l"(g));
}
__device__ __forceinline__ void cpa_commit() {
    asm volatile("cp.async.commit_group;");
}
template<int N> __device__ __forceinline__ void cpa_wait() {
    asm volatile("cp.async.wait_group %0;" :: "n"(N));
}

// ============================================================
// K1 split-K: 64 rows x 64 h x K/2 per block, 256 threads, 4x4 f32x2
//   grid (34, 4, 2) = 272 blocks -> 2 blocks/SM -> 16 warps/SM
// ============================================================
__global__ __launch_bounds__(256) void gemm_k1(
    const float* __restrict__ seg, const float* __restrict__ vid,
    const float* __restrict__ W1)
{
    __shared__ float Xs[32][68];
    __shared__ float Ws[32][68];
    const int r0 = blockIdx.x * 64;
    const int h0 = blockIdx.y * 64;
    const int kh = blockIdx.z;                 // K half
    const int t  = threadIdx.x;
    const int tm = (t >> 4) * 4;
    const int tn = (t & 15) * 4;
    const int koff = ((r0 < N_SEG) ? 0 : DDIM) + kh * KHALF;
    const float* xbase = (r0 < N_SEG) ? (seg + (size_t)r0 * DDIM)
                                      : (vid + (size_t)(r0 - N_SEG) * DDIM);

    u64 acc[4][2];
    #pragma unroll
    for (int i = 0; i < 4; i++) { acc[i][0] = 0ull; acc[i][1] = 0ull; }

    float4 xreg[2], wreg[2];
    #pragma unroll
    for (int p = 0; p < 2; p++) {
        int idx = t + p * 256;
        int rr = idx >> 3, fq = idx & 7;
        xreg[p] = *(const float4*)(xbase + (size_t)rr * DDIM + kh * KHALF + 4 * fq);
        wreg[p] = *(const float4*)(W1 + (size_t)(h0 + rr) * (2 * DDIM) + koff + 4 * fq);
    }

    for (int k0 = 0; k0 < KHALF; k0 += 32) {
        __syncthreads();
        #pragma unroll
        for (int p = 0; p < 2; p++) {
            int idx = t + p * 256;
            int rr = idx >> 3, fq = idx & 7;
            int col = rr ^ (4 * fq);
            Xs[4 * fq + 0][col] = xreg[p].x;
            Xs[4 * fq + 1][col] = xreg[p].y;
            Xs[4 * fq + 2][col] = xreg[p].z;
            Xs[4 * fq + 3][col] = xreg[p].w;
            Ws[4 * fq + 0][col] = wreg[p].x;
            Ws[4 * fq + 1][col] = wreg[p].y;
            Ws[4 * fq + 2][col] = wreg[p].z;
            Ws[4 * fq + 3][col] = wreg[p].w;
        }
        __syncthreads();
        if (k0 + 32 < KHALF) {
            #pragma unroll
            for (int p = 0; p < 2; p++) {
                int idx = t + p * 256;
                int rr = idx >> 3, fq = idx & 7;
                xreg[p] = *(const float4*)(xbase + (size_t)rr * DDIM + kh * KHALF + k0 + 32 + 4 * fq);
                wreg[p] = *(const float4*)(W1 + (size_t)(h0 + rr) * (2 * DDIM) + koff + k0 + 32 + 4 * fq);
            }
        }
        #pragma unroll
        for (int kk = 0; kk < 32; kk++) {
            int q4 = 4 * (kk >> 2);
            float4 av = *(const float4*)&Xs[kk][tm ^ q4];
            ulonglong2 wv = *(const ulonglong2*)&Ws[kk][tn ^ q4];
            u64 ad;
            ad = dup2(av.x); fma2(acc[0][0], ad, wv.x); fma2(acc[0][1], ad, wv.y);
            ad = dup2(av.y); fma2(acc[1][0], ad, wv.x); fma2(acc[1][1], ad, wv.y);
            ad = dup2(av.z); fma2(acc[2][0], ad, wv.x); fma2(acc[2][1], ad, wv.y);
            ad = dup2(av.w); fma2(acc[3][0], ad, wv.x); fma2(acc[3][1], ad, wv.y);
        }
    }

    float* Pp = kh ? g_P2 : g_P1;
    #pragma unroll
    for (int i = 0; i < 4; i++) {
        int r = r0 + tm + i;
        #pragma unroll
        for (int jp = 0; jp < 2; jp++) {
            float v0, v1;
            unpack2(acc[i][jp], v0, v1);
            int h = h0 + tn + 2 * jp;
            *(float2*)&g_P1[0];  // no-op to keep symbols; real store below
            *(float2*)&Pp[(size_t)r * HDIM + h] = make_float2(v0, v1);
        }
    }
}

// ============================================================
// reduce: g_P = g_P1 + g_P2 (+ b1 for seg rows). 544 blocks x 256, 1 float4/thr
// ============================================================
__global__ __launch_bounds__(256) void reduce_k(const float* __restrict__ b1)
{
    int idx = blockIdx.x * 256 + threadIdx.x;     // float4 index, 139264 total
    float4 a = ((const float4*)g_P1)[idx];
    float4 b = ((const float4*)g_P2)[idx];
    float4 r = make_float4(a.x + b.x, a.y + b.y, a.z + b.z, a.w + b.w);
    int fidx = idx * 4;
    if (fidx < N_SEG * HDIM) {
        int h = fidx & (HDIM - 1);
        r.x += b1[h]; r.y += b1[h + 1]; r.z += b1[h + 2]; r.w += b1[h + 3];
    }
    ((float4*)g_P)[idx] = r;
}

// ============================================================
// K2: 64 n x 32 s, BK=32, 512 threads, 2x2 scalar microtile  (frozen)
// ============================================================
__global__ __launch_bounds__(512) void fused_k2(
    const float* __restrict__ W2, const float* __restrict__ b2)
{
    __shared__ float As[32][68];
    __shared__ float Bs[32][36];
    __shared__ float w2s[32];
    const int n0 = blockIdx.x * 64;
    const int s0 = blockIdx.y * 32;
    const int t  = threadIdx.x;
    const int tn = (t & 31) * 2;
    const int ts = (t >> 5) * 2;
    const int rr = t >> 3, fq = t & 7;
    const float bb2 = b2[0];

    float acc00 = 0.f, acc01 = 0.f, acc10 = 0.f, acc11 = 0.f;

    float4 areg, breg; float wreg = 0.f;
    areg = *(const float4*)(g_P + (size_t)(n0 + rr) * HDIM + 4 * fq);
    if (t < 256) breg = *(const float4*)(g_P + (size_t)(N_SEG + s0 + rr) * HDIM + 4 * fq);
    if (t < 32)  wreg = W2[t];

    for (int k0 = 0; k0 < HDIM; k0 += 32) {
        __syncthreads();
        {
            int col = rr ^ (4 * fq);
            As[4 * fq + 0][col] = areg.x;
            As[4 * fq + 1][col] = areg.y;
            As[4 * fq + 2][col] = areg.z;
            As[4 * fq + 3][col] = areg.w;
            if (t < 256) {
                Bs[4 * fq + 0][col] = breg.x;
                Bs[4 * fq + 1][col] = breg.y;
                Bs[4 * fq + 2][col] = breg.z;
                Bs[4 * fq + 3][col] = breg.w;
            }
            if (t < 32) w2s[t] = wreg;
        }
        __syncthreads();
        if (k0 + 32 < HDIM) {
            areg = *(const float4*)(g_P + (size_t)(n0 + rr) * HDIM + k0 + 32 + 4 * fq);
            if (t < 256) breg = *(const float4*)(g_P + (size_t)(N_SEG + s0 + rr) * HDIM + k0 + 32 + 4 * fq);
            if (t < 32)  wreg = W2[k0 + 32 + t];
        }
        #pragma unroll
        for (int kk = 0; kk < 32; kk++) {
            int q4 = 4 * (kk >> 2);
            float2 an = *(const float2*)&As[kk][tn ^ q4];
            float2 bv = *(const float2*)&Bs[kk][ts ^ q4];
            float w = w2s[kk];
            acc00 += fmaxf(an.x + bv.x, 0.0f) * w;
            acc01 += fmaxf(an.x + bv.y, 0.0f) * w;
            acc10 += fmaxf(an.y + bv.x, 0.0f) * w;
            acc11 += fmaxf(an.y + bv.y, 0.0f) * w;
        }
    }

    float L[2][2] = {{acc00 + bb2, acc01 + bb2}, {acc10 + bb2, acc11 + bb2}};
    #pragma unroll
    for (int j = 0; j < 2; j++) {
        int s = s0 + ts + j;
        float L0 = L[0][j], L1 = L[1][j];
        *(float2*)&g_logitsT[(size_t)s * N_SEG + n0 + tn] = make_float2(L0, L1);
        float ls0 = fminf(L0, 0.0f) - __logf(1.0f + __expf(-fabsf(L0)));
        float ls1 = fminf(L1, 0.0f) - __logf(1.0f + __expf(-fabsf(L1)));
        *(float2*)&g_logsigT[(size_t)s * N_SEG + n0 + tn] = make_float2(ls0, ls1);
    }
}

// ============================================================
// K3 roles (256 threads) — R12 structure, DP prefetch deepened to 4:
//   warps 0-4 (t<160)  : cp.async loaders (proven protocol)
//   warp 5 (160..191)  : replay steps 15..0 of chunk c+1 (seed = bmids)
//   warp 6 (192..223)  : replay steps 31..16 of chunk c+1 (seed = bcols)
//   warp 7 (224..255)  : serial DP, no bit ops; snapshots entry + mid
// ============================================================
template<bool CLAMP>
__device__ __forceinline__ void dp_chunk(const float* __restrict__ buf, int c, int L,
                                         float& p0, float& p1, float& p2, float& p3,
                                         float* __restrict__ bmids)
{
    const int n0 = 4 * L;
    float4 pf[4];
    #pragma unroll
    for (int k = 0; k < 4; k++)
        pf[(31 - k) & 3] = *(const float4*)(buf + (31 - k) * 128 + n0);
    #pragma unroll
    for (int i = 31; i >= 0; i--) {
        float4 ls = pf[i & 3];
        if (i >= 4) pf[i & 3] = *(const float4*)(buf + (i - 4) * 128 + n0);
        float nxt3 = __shfl_down_sync(FULLMASK, p0, 1);
        if (L == 31) nxt3 = 0.0f;               // n=127 adds 0
        float c0 = ls.x + p1;
        float c1 = ls.y + p2;
        float c2 = ls.z + p3;
        float c3 = ls.w + nxt3;
        float v0 = fmaxf(c0, p0);
        float v1 = fmaxf(c1, p1);
        float v2 = fmaxf(c2, p2);
        float v3 = fmaxf(c3, p3);
        if (CLAMP) {
            int s = c * 32 + i;
            v0 = (s >= n0     && s <= 1920 + n0) ? v0 : NEGV;
            v1 = (s >= n0 + 1 && s <= 1921 + n0) ? v1 : NEGV;
            v2 = (s >= n0 + 2 && s <= 1922 + n0) ? v2 : NEGV;
            v3 = (s >= n0 + 3 && s <= 1923 + n0) ? v3 : NEGV;
        }
        p0 = v0; p1 = v1; p2 = v2; p3 = v3;
        if (i == 16)   // state after step 16 = seed for lower-half replay
            *(float4*)(bmids + c * 128 + n0) = make_float4(p0, p1, p2, p3);
    }
}

// replay steps IHI..ILO of chunk cc; identical arithmetic; emits take bits.
template<bool CLAMP, int IHI, int ILO>
__device__ __forceinline__ void replay_half(const float* __restrict__ buf, int cc, int L,
                                            const float* __restrict__ seeds,
                                            unsigned* __restrict__ bitsOut, int shift)
{
    const int n0 = 4 * L;
    float4 sv = *(const float4*)(seeds + cc * 128 + n0);
    float p0 = sv.x, p1 = sv.y, p2 = sv.z, p3 = sv.w;
    unsigned a0 = 0, a1 = 0, a2 = 0, a3 = 0;
    #pragma unroll
    for (int i = IHI; i >= ILO; i--) {
        float4 ls = *(const float4*)(buf + i * 128 + n0);
        float nxt3 = __shfl_down_sync(FULLMASK, p0, 1);
        if (L == 31) nxt3 = 0.0f;
        float c0 = ls.x + p1;
        float c1 = ls.y + p2;
        float c2 = ls.z + p3;
        float c3 = ls.w + nxt3;
        a0 = a0 + a0 + (unsigned)(c0 >= p0);
        a1 = a1 + a1 + (unsigned)(c1 >= p1);
        a2 = a2 + a2 + (unsigned)(c2 >= p2);
        a3 = a3 + a3 + (unsigned)(c3 >= p3);
        float v0 = fmaxf(c0, p0);
        float v1 = fmaxf(c1, p1);
        float v2 = fmaxf(c2, p2);
        float v3 = fmaxf(c3, p3);
        if (CLAMP) {
            int s = cc * 32 + i;
            v0 = (s >= n0     && s <= 1920 + n0) ? v0 : NEGV;
            v1 = (s >= n0 + 1 && s <= 1921 + n0) ? v1 : NEGV;
            v2 = (s >= n0 + 2 && s <= 1922 + n0) ? v2 : NEGV;
            v3 = (s >= n0 + 3 && s <= 1923 + n0) ? v3 : NEGV;
        }
        p0 = v0; p1 = v1; p2 = v2; p3 = v3;
    }
    *(uint4*)(bitsOut + cc * 128 + n0) =
        make_uint4(a0 << shift, a1 << shift, a2 << shift, a3 << shift);
}

// async loader: 160 lanes, 1024 float4s per chunk, fire-and-forget
__device__ __forceinline__ void load_chunk_async(const float* __restrict__ src,
                                                 uint32_t dst_s, int lt)
{
    #pragma unroll
    for (int j = 0; j < 7; j++) {
        int i = lt + 160 * j;
        if (i < 1024) cpa16(dst_s + i * 16, src + i * 4);
    }
    cpa_commit();
}

__global__ __launch_bounds__(256) void dp_k3(float* __restrict__ out, int out_size)
{
    extern __shared__ unsigned char smraw[];
    float*    lsbuf    = (float*)smraw;                      // [4][4096] 64KB ring
    float*    bcols    = lsbuf + 4 * 4096;                   // [64][128] 32KB
    float*    bmids    = bcols + 64 * 128;                   // [64][128] 32KB
    unsigned* bitsLo   = (unsigned*)(bmids + 64 * 128);      // [64][128] 32KB
    unsigned* bitsHi   = bitsLo + 64 * 128;                  // [64][128] 32KB
    int*      alignArr = (int*)(bitsHi + 64 * 128);          // [128]
    float*    redbuf   = (float*)(alignArr + 128);           // [4]

    const int t = threadIdx.x;
    const int L = t & 31;
    const uint32_t ls_s = smem_u32(lsbuf);

    if (t < 128) alignArr[t] = 0;
    if (t < 160) {
        load_chunk_async(g_logsigT + 63 * 4096, ls_s + (63 & 3) * 16384, t);
        load_chunk_async(g_logsigT + 62 * 4096, ls_s + (62 & 3) * 16384, t);
        cpa_wait<1>();   // chunk 63 complete before the first DP read
    }
    __syncthreads();

    float p0 = NEGV, p1 = NEGV, p2 = NEGV, p3 = NEGV;
    for (int c = 63; c >= 0; c--) {
        if (t >= 224) {
            // entry-state snapshot = seed for upper-half replay of chunk c
            *(float4*)(bcols + c * 128 + 4 * L) = make_float4(p0, p1, p2, p3);
            const float* buf = lsbuf + (c & 3) * 4096;
            if (c >= 4 && c <= 59) dp_chunk<false>(buf, c, L, p0, p1, p2, p3, bmids);
            else                   dp_chunk<true >(buf, c, L, p0, p1, p2, p3, bmids);
        } else if (t >= 192) {
            if (c < 63) {
                int cc = c + 1;
                const float* buf = lsbuf + (cc & 3) * 4096;
                if (cc >= 4 && cc <= 59) replay_half<false, 31, 16>(buf, cc, L, bcols, bitsHi, 16);
                else                     replay_half<true , 31, 16>(buf, cc, L, bcols, bitsHi, 16);
            }
        } else if (t >= 160) {
            if (c < 63) {
                int cc = c + 1;
                const float* buf = lsbuf + (cc & 3) * 4096;
                if (cc >= 4 && cc <= 59) replay_half<false, 15, 0>(buf, cc, L, bmids, bitsLo, 0);
                else                     replay_half<true , 15, 0>(buf, cc, L, bmids, bitsLo, 0);
            }
        } else {
            if (c >= 2) {
                load_chunk_async(g_logsigT + (size_t)(c - 2) * 4096,
                                 ls_s + ((c - 2) & 3) * 16384, t);
                cpa_wait<1>();   // newest pending = chunk c-2; chunk c-1 done
            } else if (c == 1) {
                cpa_wait<0>();   // chunk 0 done before final iteration
            }
        }
        __syncthreads();
    }
    // epilogue: replay chunk 0 (slot 0 untouched since it was loaded)
    if (t >= 192 && t < 224)
        replay_half<true, 31, 16>(lsbuf + 0, 0, L, bcols, bitsHi, 16);
    else if (t >= 160 && t < 192)
        replay_half<true, 15, 0>(lsbuf + 0, 0, L, bmids, bitsLo, 0);
    __syncthreads();

    // walk: first set take-bit at s >= scur per n (equivalent to ref scan)
    if (t == 0) {
        int scur = 0;
        for (int n = 0; n < 128; n++) {
            int wdi = scur >> 5;
            unsigned word = (bitsLo[wdi * 128 + n] | bitsHi[wdi * 128 + n])
                            & (0xFFFFFFFFu << (scur & 31));
            while (word == 0) {
                wdi++;
                if (wdi >= 64) break;
                word = bitsLo[wdi * 128 + n] | bitsHi[wdi * 128 + n];
            }
            if (wdi >= 64) break;
            int s = wdi * 32 + (__ffs(word) - 1);
            alignArr[n] = s;
            scur = s + 1;
            if (scur >= S_VID) break;
        }
    }
    __syncthreads();

    // outputs
    if (t < 128) {
        int a = alignArr[t];
        out[(size_t)(S_VID + t) * RTOT + a] = 1.0f;
        float v = g_logitsT[(size_t)a * N_SEG + t];
        #pragma unroll
        for (int o = 16; o; o >>= 1) v += __shfl_down_sync(FULLMASK, v, o);
        if ((t & 31) == 0) redbuf[t >> 5] = v;
    }
    __syncthreads();
    if (t == 0) {
        float sum = redbuf[0] + redbuf[1] + redbuf[2] + redbuf[3];
        if (out_size > RTOT * RTOT) out[(size_t)RTOT * RTOT] = sum * (1.0f / 128.0f);
    }
}

// ============================================================
extern "C" void kernel_launch(void* const* d_in, const int* in_sizes, int n_in,
                              void* d_out, int out_size)
{
    const float* seg = (const float*)d_in[0];
    const float* vid = (const float*)d_in[1];
    const float* W1  = (const float*)d_in[2];
    const float* b1  = (const float*)d_in[3];
    const float* W2  = (const float*)d_in[4];
    const float* b2  = (const float*)d_in[5];
    float* out = (float*)d_out;

    cudaMemsetAsync(out, 0, (size_t)out_size * sizeof(float), 0);  // ~2 launches
    gemm_k1<<<dim3(34, 4, 2), 256>>>(seg, vid, W1);
    reduce_k<<<544, 256>>>(b1);
    fused_k2<<<dim3(2, 64), 512>>>(W2, b2);

    const int smem_k3 = (4 * 4096 + 2 * 64 * 128) * 4 + 2 * 64 * 128 * 4 + 128 * 4 + 4 * 4;
    cudaFuncSetAttribute(dp_k3, cudaFuncAttributeMaxDynamicSharedMemorySize, smem_k3);
    dp_k3<<<1, 256, smem_k3>>>(out, out_size);
}